// round 6
// baseline (speedup 1.0000x reference)
#include <cuda_runtime.h>

#define NB 256
#define XB 256
#define TB 3
#define KB 64
#define AB 193
#define EPSF 1e-9f

#define MAIN_BLOCKS 6528
#define ROWHALF 98304              // 98304*17 = 6528*256
#define TOTAL_BLOCKS (MAIN_BLOCKS + NB)
#define MASK_WORDS 6144            // 196608 rows / 32

__device__ float    g_part[TOTAL_BLOCKS];
__device__ unsigned g_count = 0;
__device__ unsigned g_mask[MASK_WORDS];

// ---------------------------------------------------------------------------
// Pre-kernel: bitmask of gt_class>0 per row (one bit per (n,x,t) row).
// Removes the 600-cycle DRAM dependency from the main kernel's loss2 gate.
// ---------------------------------------------------------------------------
__global__ void __launch_bounds__(256) k_mask(const float* __restrict__ gt) {
    int r = blockIdx.x * 256 + threadIdx.x;          // grid = 768 blocks
    float gc = __ldg(gt + (size_t)r * AB + 192);
    unsigned b = __ballot_sync(0xffffffffu, gc > 0.f);
    if ((threadIdx.x & 31) == 0) g_mask[r >> 5] = b;
}

// ---------------------------------------------------------------------------
// Fused kernel. Main path: gate from L1-resident bitmask -> all loads issue
// as an independent front batch (full MLP) while bytes stay gated.
//  blockIdx <  NB : per-batch lane-geometry losses (loss3, loss4)
//  blockIdx >= NB : elementwise losses (loss0, loss1, loss2), 2 units/thread
// ---------------------------------------------------------------------------
__global__ void __launch_bounds__(256, 7) k_fused(
    const float* __restrict__ pred, const float* __restrict__ gt,
    const float* __restrict__ hcam_arr, const float* __restrict__ ax,
    const float* __restrict__ ay, const float* __restrict__ xstd,
    const float* __restrict__ zstd, float* __restrict__ out)
{
    const int tid  = threadIdx.x;
    const int lane = tid & 31;
    const int wid  = tid >> 5;
    const unsigned FULL = 0xffffffffu;

    __shared__ float s_w8[8];

    float partial = 0.f;

    if (blockIdx.x >= NB) {
        // =============== MAIN PATH: loss0 + loss1 + loss2 ===============
        const int gid = (blockIdx.x - NB) * 256 + tid;
        int row = gid / 17;
        int j   = gid - row * 17;
        int a   = row & 3;
        int k0  = 4 * j - a;

        const int bx1 = row * AB - a + 4 * j;       // 16B-aligned xoff window
        const int bx2 = bx1 + ROWHALF * AB;

        // cheap gate loads (24KB table, L1/L2 resident, warp-broadcast)
        const int  w1 = row >> 5;
        const unsigned bit = 1u << (row & 31);      // (row+98304)&31 == row&31
        unsigned m1 = g_mask[w1];
        unsigned m2 = g_mask[w1 + (ROWHALF >> 5)];

        // unconditional vis loads (front batch)
        float4 pvA = *reinterpret_cast<const float4*>(pred + bx1 + 128);
        float4 gvA = *reinterpret_cast<const float4*>(gt   + bx1 + 128);
        float4 pvB = *reinterpret_cast<const float4*>(pred + bx2 + 128);
        float4 gvB = *reinterpret_cast<const float4*>(gt   + bx2 + 128);

        const bool l1 = (m1 & bit) != 0u;
        const bool l2 = (m2 & bit) != 0u;

        // gated xoff loads for unit 1: issue before any math
        float4 pxA = make_float4(0.f, 0.f, 0.f, 0.f);
        float4 gxA = pxA;
        if (l1) {
            pxA = *reinterpret_cast<const float4*>(pred + bx1);
            gxA = *reinterpret_cast<const float4*>(gt   + bx1);
        }

        float acc = 0.f;

        {   // ---- unit 1 BCE (hides unit-1 xoff latency) ----
            float pvs[4] = {pvA.x, pvA.y, pvA.z, pvA.w};
            float gvs[4] = {gvA.x, gvA.y, gvA.z, gvA.w};
#pragma unroll
            for (int i = 0; i < 4; i++) {
                int k = k0 + i;
                float pv = pvs[i];
                bool g1 = gvs[i] > 0.5f;
                float arg = g1 ? (pv + EPSF) : (1.f - pv + EPSF);
                if ((unsigned)k < 64u) {
                    float cf = g1 ? (1.f / 64.f) : ((1.f + EPSF) / 64.f);
                    acc -= cf * __logf(arg);
                } else if (k == 64) {              // class scalar: loss1, exact
                    acc -= __logf(arg);
                }
            }

            // gated xoff loads for unit 2: issue before unit-1 loss2 math
            float4 pxB = make_float4(0.f, 0.f, 0.f, 0.f);
            float4 gxB = pxB;
            if (l2) {
                pxB = *reinterpret_cast<const float4*>(pred + bx2);
                gxB = *reinterpret_cast<const float4*>(gt   + bx2);
            }

            if (l1) {                              // loss2 unit 1 (gc==1)
                float pxs[4] = {pxA.x, pxA.y, pxA.z, pxA.w};
                float gxs[4] = {gxA.x, gxA.y, gxA.z, gxA.w};
#pragma unroll
                for (int i = 0; i < 4; i++)
                    if ((unsigned)(k0 + i) < 64u)
                        acc += gvs[i] * fabsf(pxs[i] - gxs[i]);
            }

            // ---- unit 2 BCE ----
            float pvs2[4] = {pvB.x, pvB.y, pvB.z, pvB.w};
            float gvs2[4] = {gvB.x, gvB.y, gvB.z, gvB.w};
#pragma unroll
            for (int i = 0; i < 4; i++) {
                int k = k0 + i;
                float pv = pvs2[i];
                bool g1 = gvs2[i] > 0.5f;
                float arg = g1 ? (pv + EPSF) : (1.f - pv + EPSF);
                if ((unsigned)k < 64u) {
                    float cf = g1 ? (1.f / 64.f) : ((1.f + EPSF) / 64.f);
                    acc -= cf * __logf(arg);
                } else if (k == 64) {
                    acc -= __logf(arg);
                }
            }
            if (l2) {                              // loss2 unit 2
                float pxs[4] = {pxB.x, pxB.y, pxB.z, pxB.w};
                float gxs[4] = {gxB.x, gxB.y, gxB.z, gxB.w};
#pragma unroll
                for (int i = 0; i < 4; i++)
                    if ((unsigned)(k0 + i) < 64u)
                        acc += gvs2[i] * fabsf(pxs[i] - gxs[i]);
            }
        }

        // warp reduce + cross-warp via smem
#pragma unroll
        for (int o = 16; o > 0; o >>= 1)
            acc += __shfl_xor_sync(FULL, acc, o);
        if (lane == 0) s_w8[wid] = acc;
        __syncthreads();
        if (tid == 0) {
            float s = 0.f;
#pragma unroll
            for (int w = 0; w < 8; w++) s += s_w8[w];
            partial = s;
        }
    } else {
        // =============== LANES PATH: loss3 + loss4 (x5) ===============
        const int n = blockIdx.x;
        __shared__ int   s_sel[XB];
        __shared__ int   s_nsel;
        __shared__ int   s_wcnt[8];
        __shared__ int   s_rowoff[768];
        __shared__ float s_ax[768];
        __shared__ float s_cs[4][KB];
        __shared__ int   s_ck[KB];
        __shared__ int   s_ncols;
        __shared__ float s_lw[8], s_lh[8];

        const float* gtn = gt   + (size_t)n * XB * TB * AB;
        const float* prn = pred + (size_t)n * XB * TB * AB;

        // step 1: stable compaction of sel = gt_class[:,t=0] > 0
        {
            int x = tid;
            float gc0 = gtn[(size_t)x * TB * AB + (AB - 1)];
            bool sel = gc0 > 0.f;
            unsigned b = __ballot_sync(FULL, sel);
            if (lane == 0) s_wcnt[wid] = __popc(b);
            __syncthreads();
            int wbase = 0;
#pragma unroll
            for (int w = 0; w < 8; w++) wbase += (w < wid) ? s_wcnt[w] : 0;
            int pos = wbase + __popc(b & ((1u << lane) - 1u));
            if (sel) s_sel[pos] = x;
            if (tid == 255) s_nsel = pos + (sel ? 1 : 0);
            __syncthreads();
        }
        const int nsel  = s_nsel;
        const int nrows = nsel * 3;

        for (int r = tid; r < nrows; r += 256) {
            int q = r / 3, t = r - q * 3;
            int x = s_sel[q];
            s_rowoff[r] = (x * TB + t) * AB;
            s_ax[r]     = ax[x];
        }
        __syncthreads();

        // step 2: col_sum over selected rows; keep; stable column compaction
        {
            int k = tid & 63, part = tid >> 6;
            float cs = 0.f;
            for (int r = part; r < nrows; r += 4)
                cs += gtn[s_rowoff[r] + 128 + k];
            s_cs[part][k] = cs;
            __syncthreads();
            if (tid == 0) {
                int nc = 0;
                float nf = (float)nrows;
                for (int kk = 0; kk < KB; kk++) {
                    float tot = s_cs[0][kk] + s_cs[1][kk] + s_cs[2][kk] + s_cs[3][kk];
                    if (tot >= nf || kk < 5) s_ck[nc++] = kk;
                }
                s_ncols = nc;
            }
            __syncthreads();
        }
        const int   ncols = s_ncols;   // always >= 5
        const float hcam  = hcam_arr[n];
        const float xstd0 = xstd[0];

        float lwacc = 0.f, lhacc = 0.f;
        const int npairs = nrows - 1;

        if (ncols <= 8) {
            const int sl  = lane & 7;
            const int seg = lane >> 3;
            for (int i0 = wid * 4; i0 < npairs; i0 += 32) {
                int  i      = i0 + seg;
                bool pvalid = i < npairs;
                int  ii     = pvalid ? i : 0;
                int offA = s_rowoff[ii],     offB = s_rowoff[ii + 1];
                float axA = s_ax[ii],        axB  = s_ax[ii + 1];
                const float* pA = prn + offA;
                const float* gA = gtn + offA;
                const float* pB = prn + offB;
                const float* gB = gtn + offB;

                float width0 = fabsf((gB[0] * xstd0 + axB) - (gA[0] * xstd0 + axA));

                bool act = pvalid && (sl < ncols);
                int  c   = s_ck[sl < ncols ? sl : (ncols - 1)];
                float zsd = zstd[c];
                float ZA = pA[KB + c] * zsd;
                float ZB = pB[KB + c] * zsd;
                float sA = 1.f - ZA / hcam;
                float sB = 1.f - ZB / hcam;
                float laneA = sA * (gA[c] * xstd[c] + axA);
                float laneB = sB * (gB[c] * xstd[c] + axB);
                float YA = sA * ay[c];

                float pl = __shfl_up_sync(FULL, laneA, 1, 8);
                float py = __shfl_up_sync(FULL, YA, 1, 8);
                float ddy = YA - py;
                float ddl = laneA - pl;
                float dy  = fabsf(ddy);
                float dxy = sqrtf(ddl * ddl + ddy * ddy);
                float lY = dy, l = dxy;
                float dy1 = __shfl_sync(FULL, dy, 1, 8);
                if (sl == 0) { lY = dy1; l = dy1; }
                float w  = fabsf(laneB - laneA) * lY / (l + EPSF);
                float pw = __shfl_up_sync(FULL, w, 1, 8);
                if (sl == 0) pw = width0;
                if (act) {
                    lwacc += fabsf(w - pw);
                    lhacc += fabsf(ZB - ZA);
                }
            }
        } else {
            for (int i = wid; i < npairs; i += 8) {
                int offA = s_rowoff[i],  offB = s_rowoff[i + 1];
                float axA = s_ax[i],     axB  = s_ax[i + 1];
                const float* pA = prn + offA;
                const float* gA = gtn + offA;
                const float* pB = prn + offB;
                const float* gB = gtn + offB;

                float w_prev_carry = fabsf((gB[0] * xstd0 + axB) - (gA[0] * xstd0 + axA));
                float carry_lane = 0.f, carry_Y = 0.f;

                for (int jb = 0; jb < ncols; jb += 32) {
                    int  jj  = jb + lane;
                    bool act = jj < ncols;
                    int  c   = s_ck[act ? jj : (ncols - 1)];
                    float zsd = zstd[c];
                    float ZA = pA[KB + c] * zsd;
                    float ZB = pB[KB + c] * zsd;
                    float sA = 1.f - ZA / hcam;
                    float sB = 1.f - ZB / hcam;
                    float laneA = sA * (gA[c] * xstd[c] + axA);
                    float laneB = sB * (gB[c] * xstd[c] + axB);
                    float YA = sA * ay[c];

                    float pl = __shfl_up_sync(FULL, laneA, 1);
                    float py = __shfl_up_sync(FULL, YA, 1);
                    if (lane == 0) { pl = carry_lane; py = carry_Y; }
                    float ddy = YA - py;
                    float ddl = laneA - pl;
                    float dy  = fabsf(ddy);
                    float dxy = sqrtf(ddl * ddl + ddy * ddy);
                    float lY = dy, l = dxy;
                    if (jb == 0) {
                        float dy1 = __shfl_sync(FULL, dy, 1);
                        if (lane == 0) { lY = dy1; l = dy1; }
                    }
                    float w  = fabsf(laneB - laneA) * lY / (l + EPSF);
                    float pw = __shfl_up_sync(FULL, w, 1);
                    if (lane == 0) pw = w_prev_carry;
                    if (act) {
                        lwacc += fabsf(w - pw);
                        lhacc += fabsf(ZB - ZA);
                    }
                    carry_lane   = __shfl_sync(FULL, laneA, 31);
                    carry_Y      = __shfl_sync(FULL, YA, 31);
                    w_prev_carry = __shfl_sync(FULL, w, 31);
                }
            }
        }

#pragma unroll
        for (int o = 16; o > 0; o >>= 1) {
            lwacc += __shfl_xor_sync(FULL, lwacc, o);
            lhacc += __shfl_xor_sync(FULL, lhacc, o);
        }
        if (lane == 0) { s_lw[wid] = lwacc; s_lh[wid] = lhacc; }
        __syncthreads();
        if (tid == 0) {
            float lw = 0.f, lh = 0.f;
#pragma unroll
            for (int w = 0; w < 8; w++) { lw += s_lw[w]; lh += s_lh[w]; }
            partial = 5.f * (lw + lh);
        }
    }

    // ---------------- publish partial + last-block final reduction ----------
    __shared__ bool s_last;
    if (tid == 0) {
        g_part[blockIdx.x] = partial;
        __threadfence();
        unsigned old = atomicAdd(&g_count, 1u);
        s_last = (old == TOTAL_BLOCKS - 1);
    }
    __syncthreads();

    if (s_last) {
        __threadfence();
        __shared__ double sd[256];
        double s = 0.0;
        for (int i = tid; i < TOTAL_BLOCKS; i += 256) s += (double)g_part[i];
        sd[tid] = s;
        __syncthreads();
        for (int o = 128; o > 0; o >>= 1) {
            if (tid < o) sd[tid] += sd[tid + o];
            __syncthreads();
        }
        if (tid == 0) {
            out[0] = (float)sd[0];
            g_count = 0;             // reset for next graph replay
        }
    }
}

extern "C" void kernel_launch(void* const* d_in, const int* in_sizes, int n_in,
                              void* d_out, int out_size) {
    const float* pred = (const float*)d_in[0];
    const float* gt   = (const float*)d_in[1];
    const float* hcam = (const float*)d_in[2];
    const float* axs  = (const float*)d_in[3];
    const float* ays  = (const float*)d_in[4];
    const float* xstd = (const float*)d_in[5];
    const float* zstd = (const float*)d_in[6];

    k_mask <<<768, 256>>>(gt);
    k_fused<<<TOTAL_BLOCKS, 256>>>(pred, gt, hcam, axs, ays, xstd, zstd,
                                   (float*)d_out);
}

// round 7
// speedup vs baseline: 1.1033x; 1.1033x over previous
#include <cuda_runtime.h>

#define NB 256
#define XB 256
#define TB 3
#define KB 64
#define AB 193
#define EPSF 1e-9f

#define MAIN_BLOCKS 6528
#define ROWHALF 98304              // 98304*17 = 6528*256
#define TOTAL_BLOCKS (MAIN_BLOCKS + NB)

__device__ float    g_part[TOTAL_BLOCKS];
__device__ unsigned g_count = 0;

// ---------------------------------------------------------------------------
// Fused kernel. Main path: ALL loads unconditional and independent (this is
// what sustains ~6 TB/s; every gating variant measured slower). Single-log
// BCE exploits gt_vis/gt_class in {0,1}. loss2 scaled by gc numerically.
//  blockIdx <  NB : per-batch lane-geometry losses (loss3, loss4)
//  blockIdx >= NB : elementwise losses (loss0, loss1, loss2), 2 units/thread
// ---------------------------------------------------------------------------
__global__ void __launch_bounds__(256, 8) k_fused(
    const float* __restrict__ pred, const float* __restrict__ gt,
    const float* __restrict__ hcam_arr, const float* __restrict__ ax,
    const float* __restrict__ ay, const float* __restrict__ xstd,
    const float* __restrict__ zstd, float* __restrict__ out)
{
    const int tid  = threadIdx.x;
    const int lane = tid & 31;
    const int wid  = tid >> 5;
    const unsigned FULL = 0xffffffffu;

    __shared__ float s_w8[8];

    float partial = 0.f;

    if (blockIdx.x >= NB) {
        // =============== MAIN PATH: loss0 + loss1 + loss2 ===============
        const int gid = (blockIdx.x - NB) * 256 + tid;
        const int row = gid / 17;
        const int j   = gid - row * 17;
        const int a   = row & 3;               // (row+98304)&3 == row&3
        const int k0  = 4 * j - a;

        const int rb1 = row * AB;
        const int rb2 = rb1 + ROWHALF * AB;
        const int bx1 = rb1 - a + 4 * j;       // 16B-aligned xoff window
        const int bx2 = bx1 + ROWHALF * AB;

        float acc = 0.f;

        // ---- unit 1: independent front-batched loads ----
        {
            float4 pv4 = *reinterpret_cast<const float4*>(pred + bx1 + 128);
            float4 gv4 = *reinterpret_cast<const float4*>(gt   + bx1 + 128);
            float4 px4 = *reinterpret_cast<const float4*>(pred + bx1);
            float4 gx4 = *reinterpret_cast<const float4*>(gt   + bx1);
            float  gc  = __ldg(gt + rb1 + 192);

            float pvs[4] = {pv4.x, pv4.y, pv4.z, pv4.w};
            float gvs[4] = {gv4.x, gv4.y, gv4.z, gv4.w};
            float pxs[4] = {px4.x, px4.y, px4.z, px4.w};
            float gxs[4] = {gx4.x, gx4.y, gx4.z, gx4.w};
#pragma unroll
            for (int i = 0; i < 4; i++) {
                int k = k0 + i;
                float pv = pvs[i];
                bool g1 = gvs[i] > 0.5f;
                float arg = g1 ? (pv + EPSF) : (1.f - pv + EPSF);
                if ((unsigned)k < 64u) {
                    float cf = g1 ? (1.f / 64.f) : ((1.f + EPSF) / 64.f);
                    acc -= cf * __logf(arg);
                    acc += gc * gvs[i] * fabsf(pxs[i] - gxs[i]);
                } else if (k == 64) {          // class scalar: loss1 (exact)
                    acc -= __logf(arg);
                }
            }
        }

        // ---- unit 2 ----
        {
            float4 pv4 = *reinterpret_cast<const float4*>(pred + bx2 + 128);
            float4 gv4 = *reinterpret_cast<const float4*>(gt   + bx2 + 128);
            float4 px4 = *reinterpret_cast<const float4*>(pred + bx2);
            float4 gx4 = *reinterpret_cast<const float4*>(gt   + bx2);
            float  gc  = __ldg(gt + rb2 + 192);

            float pvs[4] = {pv4.x, pv4.y, pv4.z, pv4.w};
            float gvs[4] = {gv4.x, gv4.y, gv4.z, gv4.w};
            float pxs[4] = {px4.x, px4.y, px4.z, px4.w};
            float gxs[4] = {gx4.x, gx4.y, gx4.z, gx4.w};
#pragma unroll
            for (int i = 0; i < 4; i++) {
                int k = k0 + i;
                float pv = pvs[i];
                bool g1 = gvs[i] > 0.5f;
                float arg = g1 ? (pv + EPSF) : (1.f - pv + EPSF);
                if ((unsigned)k < 64u) {
                    float cf = g1 ? (1.f / 64.f) : ((1.f + EPSF) / 64.f);
                    acc -= cf * __logf(arg);
                    acc += gc * gvs[i] * fabsf(pxs[i] - gxs[i]);
                } else if (k == 64) {
                    acc -= __logf(arg);
                }
            }
        }

        // warp reduce + cross-warp via smem
#pragma unroll
        for (int o = 16; o > 0; o >>= 1)
            acc += __shfl_xor_sync(FULL, acc, o);
        if (lane == 0) s_w8[wid] = acc;
        __syncthreads();
        if (tid == 0) {
            float s = 0.f;
#pragma unroll
            for (int w = 0; w < 8; w++) s += s_w8[w];
            partial = s;
        }
    } else {
        // =============== LANES PATH: loss3 + loss4 (x5) ===============
        const int n = blockIdx.x;
        __shared__ int   s_sel[XB];
        __shared__ int   s_nsel;
        __shared__ int   s_wcnt[8];
        __shared__ int   s_rowoff[768];
        __shared__ float s_ax[768];
        __shared__ float s_cs[4][KB];
        __shared__ int   s_ck[KB];
        __shared__ int   s_ncols;
        __shared__ float s_lw[8], s_lh[8];

        const float* gtn = gt   + (size_t)n * XB * TB * AB;
        const float* prn = pred + (size_t)n * XB * TB * AB;

        // step 1: stable compaction of sel = gt_class[:,t=0] > 0
        {
            int x = tid;
            float gc0 = gtn[(size_t)x * TB * AB + (AB - 1)];
            bool sel = gc0 > 0.f;
            unsigned b = __ballot_sync(FULL, sel);
            if (lane == 0) s_wcnt[wid] = __popc(b);
            __syncthreads();
            int wbase = 0;
#pragma unroll
            for (int w = 0; w < 8; w++) wbase += (w < wid) ? s_wcnt[w] : 0;
            int pos = wbase + __popc(b & ((1u << lane) - 1u));
            if (sel) s_sel[pos] = x;
            if (tid == 255) s_nsel = pos + (sel ? 1 : 0);
            __syncthreads();
        }
        const int nsel  = s_nsel;
        const int nrows = nsel * 3;

        for (int r = tid; r < nrows; r += 256) {
            int q = r / 3, t = r - q * 3;
            int x = s_sel[q];
            s_rowoff[r] = (x * TB + t) * AB;
            s_ax[r]     = ax[x];
        }
        __syncthreads();

        // step 2: col_sum over selected rows; keep; stable column compaction
        {
            int k = tid & 63, part = tid >> 6;
            float cs = 0.f;
            for (int r = part; r < nrows; r += 4)
                cs += gtn[s_rowoff[r] + 128 + k];
            s_cs[part][k] = cs;
            __syncthreads();
            if (tid == 0) {
                int nc = 0;
                float nf = (float)nrows;
                for (int kk = 0; kk < KB; kk++) {
                    float tot = s_cs[0][kk] + s_cs[1][kk] + s_cs[2][kk] + s_cs[3][kk];
                    if (tot >= nf || kk < 5) s_ck[nc++] = kk;
                }
                s_ncols = nc;
            }
            __syncthreads();
        }
        const int   ncols = s_ncols;   // always >= 5
        const float hcam  = hcam_arr[n];
        const float xstd0 = xstd[0];

        float lwacc = 0.f, lhacc = 0.f;
        const int npairs = nrows - 1;

        if (ncols <= 8) {
            const int sl  = lane & 7;
            const int seg = lane >> 3;
            for (int i0 = wid * 4; i0 < npairs; i0 += 32) {
                int  i      = i0 + seg;
                bool pvalid = i < npairs;
                int  ii     = pvalid ? i : 0;
                int offA = s_rowoff[ii],     offB = s_rowoff[ii + 1];
                float axA = s_ax[ii],        axB  = s_ax[ii + 1];
                const float* pA = prn + offA;
                const float* gA = gtn + offA;
                const float* pB = prn + offB;
                const float* gB = gtn + offB;

                float width0 = fabsf((gB[0] * xstd0 + axB) - (gA[0] * xstd0 + axA));

                bool act = pvalid && (sl < ncols);
                int  c   = s_ck[sl < ncols ? sl : (ncols - 1)];
                float zsd = zstd[c];
                float ZA = pA[KB + c] * zsd;
                float ZB = pB[KB + c] * zsd;
                float sA = 1.f - ZA / hcam;
                float sB = 1.f - ZB / hcam;
                float laneA = sA * (gA[c] * xstd[c] + axA);
                float laneB = sB * (gB[c] * xstd[c] + axB);
                float YA = sA * ay[c];

                float pl = __shfl_up_sync(FULL, laneA, 1, 8);
                float py = __shfl_up_sync(FULL, YA, 1, 8);
                float ddy = YA - py;
                float ddl = laneA - pl;
                float dy  = fabsf(ddy);
                float dxy = sqrtf(ddl * ddl + ddy * ddy);
                float lY = dy, l = dxy;
                float dy1 = __shfl_sync(FULL, dy, 1, 8);
                if (sl == 0) { lY = dy1; l = dy1; }
                float w  = fabsf(laneB - laneA) * lY / (l + EPSF);
                float pw = __shfl_up_sync(FULL, w, 1, 8);
                if (sl == 0) pw = width0;
                if (act) {
                    lwacc += fabsf(w - pw);
                    lhacc += fabsf(ZB - ZA);
                }
            }
        } else {
            for (int i = wid; i < npairs; i += 8) {
                int offA = s_rowoff[i],  offB = s_rowoff[i + 1];
                float axA = s_ax[i],     axB  = s_ax[i + 1];
                const float* pA = prn + offA;
                const float* gA = gtn + offA;
                const float* pB = prn + offB;
                const float* gB = gtn + offB;

                float w_prev_carry = fabsf((gB[0] * xstd0 + axB) - (gA[0] * xstd0 + axA));
                float carry_lane = 0.f, carry_Y = 0.f;

                for (int jb = 0; jb < ncols; jb += 32) {
                    int  jj  = jb + lane;
                    bool act = jj < ncols;
                    int  c   = s_ck[act ? jj : (ncols - 1)];
                    float zsd = zstd[c];
                    float ZA = pA[KB + c] * zsd;
                    float ZB = pB[KB + c] * zsd;
                    float sA = 1.f - ZA / hcam;
                    float sB = 1.f - ZB / hcam;
                    float laneA = sA * (gA[c] * xstd[c] + axA);
                    float laneB = sB * (gB[c] * xstd[c] + axB);
                    float YA = sA * ay[c];

                    float pl = __shfl_up_sync(FULL, laneA, 1);
                    float py = __shfl_up_sync(FULL, YA, 1);
                    if (lane == 0) { pl = carry_lane; py = carry_Y; }
                    float ddy = YA - py;
                    float ddl = laneA - pl;
                    float dy  = fabsf(ddy);
                    float dxy = sqrtf(ddl * ddl + ddy * ddy);
                    float lY = dy, l = dxy;
                    if (jb == 0) {
                        float dy1 = __shfl_sync(FULL, dy, 1);
                        if (lane == 0) { lY = dy1; l = dy1; }
                    }
                    float w  = fabsf(laneB - laneA) * lY / (l + EPSF);
                    float pw = __shfl_up_sync(FULL, w, 1);
                    if (lane == 0) pw = w_prev_carry;
                    if (act) {
                        lwacc += fabsf(w - pw);
                        lhacc += fabsf(ZB - ZA);
                    }
                    carry_lane   = __shfl_sync(FULL, laneA, 31);
                    carry_Y      = __shfl_sync(FULL, YA, 31);
                    w_prev_carry = __shfl_sync(FULL, w, 31);
                }
            }
        }

#pragma unroll
        for (int o = 16; o > 0; o >>= 1) {
            lwacc += __shfl_xor_sync(FULL, lwacc, o);
            lhacc += __shfl_xor_sync(FULL, lhacc, o);
        }
        if (lane == 0) { s_lw[wid] = lwacc; s_lh[wid] = lhacc; }
        __syncthreads();
        if (tid == 0) {
            float lw = 0.f, lh = 0.f;
#pragma unroll
            for (int w = 0; w < 8; w++) { lw += s_lw[w]; lh += s_lh[w]; }
            partial = 5.f * (lw + lh);
        }
    }

    // ---------------- publish partial + last-block final reduction ----------
    __shared__ bool s_last;
    if (tid == 0) {
        g_part[blockIdx.x] = partial;
        __threadfence();
        unsigned old = atomicAdd(&g_count, 1u);
        s_last = (old == TOTAL_BLOCKS - 1);
    }
    __syncthreads();

    if (s_last) {
        __threadfence();
        __shared__ double sd[256];
        double s = 0.0;
        for (int i = tid; i < TOTAL_BLOCKS; i += 256) s += (double)g_part[i];
        sd[tid] = s;
        __syncthreads();
        for (int o = 128; o > 0; o >>= 1) {
            if (tid < o) sd[tid] += sd[tid + o];
            __syncthreads();
        }
        if (tid == 0) {
            out[0] = (float)sd[0];
            g_count = 0;             // reset for next graph replay
        }
    }
}

extern "C" void kernel_launch(void* const* d_in, const int* in_sizes, int n_in,
                              void* d_out, int out_size) {
    const float* pred = (const float*)d_in[0];
    const float* gt   = (const float*)d_in[1];
    const float* hcam = (const float*)d_in[2];
    const float* axs  = (const float*)d_in[3];
    const float* ays  = (const float*)d_in[4];
    const float* xstd = (const float*)d_in[5];
    const float* zstd = (const float*)d_in[6];

    k_fused<<<TOTAL_BLOCKS, 256>>>(pred, gt, hcam, axs, ays, xstd, zstd,
                                   (float*)d_out);
}